// round 16
// baseline (speedup 1.0000x reference)
#include <cuda_runtime.h>
#include <cuda_fp16.h>
#include <cstdint>
#include <cstddef>

#define SS 1024
#define EE 1024
#define L3E 3072

// ---------------- scratch (device globals; no cudaMalloc allowed) ----------
__device__ __half g_xh[4194304],  g_xl[4194304];    // x split [tok][1024]
__device__ __half g_wqh[3145728];                   // W_qkv^T hi [n=3072][k=1024]
__device__ __half g_woh[1048576];                   // W_out^T hi [n=1024][k=1024]
__device__ __half g_qh[12582912], g_ql[12582912];   // qkv split [tok][3072]
__device__ __half g_kth[4194304];                   // K^T hi [bh][c=64][y=1024]
__device__ __half g_vth[4194304], g_vtl[4194304];   // V^T split [bh][d=64][y=1024]
__device__ __half g_m1h[262144];                    // M1^T=0.125*V^T K hi [bh][d][c]
__device__ __half g_P16[67108864];                  // P_pe fp16 [bh][x][y]
__device__ __half g_ah[4194304],  g_al[4194304];    // attn split [tok][1024]

// ---------------- helpers ---------------------------------------------------
__device__ __forceinline__ uint32_t smem_u32(const void* p) {
    uint32_t a;
    asm("{ .reg .u64 t; cvta.to.shared.u64 t, %1; cvt.u32.u64 %0, t; }" : "=r"(a) : "l"(p));
    return a;
}
__device__ __forceinline__ void split2h(float v, __half& h, __half& l) {
    h = __float2half_rn(v);
    l = __float2half_rn(v - __half2float(h));
}
__device__ __forceinline__ void store_split2(__half* Hp, __half* Lp,
                                             size_t off, float v0, float v1) {
    __half h0, l0, h1, l1;
    split2h(v0, h0, l0); split2h(v1, h1, l1);
    __half2 hh; hh.x = h0; hh.y = h1;
    __half2 ll; ll.x = l0; ll.y = l1;
    *(__half2*)(Hp + off) = hh;
    *(__half2*)(Lp + off) = ll;
}

__device__ __forceinline__ void ldsm4(uint32_t (&r)[4], uint32_t addr) {
    asm volatile("ldmatrix.sync.aligned.m8n8.x4.shared.b16 {%0,%1,%2,%3}, [%4];"
        : "=r"(r[0]), "=r"(r[1]), "=r"(r[2]), "=r"(r[3]) : "r"(addr));
}
__device__ __forceinline__ void mma16816(float (&d)[4], const uint32_t (&a)[4],
                                         uint32_t b0, uint32_t b1) {
    asm volatile(
        "mma.sync.aligned.m16n8k16.row.col.f32.f16.f16.f32 "
        "{%0,%1,%2,%3}, {%4,%5,%6,%7}, {%8,%9}, {%0,%1,%2,%3};"
        : "+f"(d[0]), "+f"(d[1]), "+f"(d[2]), "+f"(d[3])
        : "r"(a[0]), "r"(a[1]), "r"(a[2]), "r"(a[3]), "r"(b0), "r"(b1));
}

// warp-level K-block: A split (hi+lo) x B hi
template<int NJ, int STRIDE, int KS>
__device__ __forceinline__ void warp_kblk(float (&acc)[2][NJ * 2][4],
    uint32_t aAh, uint32_t aAl, uint32_t aBh)
{
    #pragma unroll
    for (int s = 0; s < KS; s++) {
        uint32_t ah[2][4], al[2][4];
        #pragma unroll
        for (int i = 0; i < 2; i++) {
            ldsm4(ah[i], aAh + i * 16 * STRIDE + s * 32);
            ldsm4(al[i], aAl + i * 16 * STRIDE + s * 32);
        }
        #pragma unroll
        for (int j = 0; j < NJ; j++) {
            uint32_t bh[4];
            ldsm4(bh, aBh + j * 16 * STRIDE + s * 32);
            #pragma unroll
            for (int i = 0; i < 2; i++) {
                mma16816(acc[i][2 * j],     ah[i], bh[0], bh[1]);
                mma16816(acc[i][2 * j + 1], ah[i], bh[2], bh[3]);
                mma16816(acc[i][2 * j],     al[i], bh[0], bh[1]);
                mma16816(acc[i][2 * j + 1], al[i], bh[2], bh[3]);
            }
        }
    }
}

// warp-level K-block, plain single fp16 A x B
template<int NJ, int STRIDE, int KS>
__device__ __forceinline__ void warp_kblk1(float (&acc)[2][NJ * 2][4],
    uint32_t aA, uint32_t aB)
{
    #pragma unroll
    for (int s = 0; s < KS; s++) {
        uint32_t a[2][4];
        #pragma unroll
        for (int i = 0; i < 2; i++)
            ldsm4(a[i], aA + i * 16 * STRIDE + s * 32);
        #pragma unroll
        for (int j = 0; j < NJ; j++) {
            uint32_t b[4];
            ldsm4(b, aB + j * 16 * STRIDE + s * 32);
            #pragma unroll
            for (int i = 0; i < 2; i++) {
                mma16816(acc[i][2 * j],     a[i], b[0], b[1]);
                mma16816(acc[i][2 * j + 1], a[i], b[2], b[3]);
            }
        }
    }
}

// async gmem [rows][32 fp16] -> smem rows of 80 bytes
__device__ __forceinline__ void cp32(uint32_t dst, const __half* src,
                                     size_t sstride, int rows, int t) {
    for (int i = t; i < rows * 4; i += 256) {
        int r = i >> 2, c = i & 3;
        asm volatile("cp.async.cg.shared.global [%0], [%1], 16;"
            :: "r"(dst + (uint32_t)(r * 80 + c * 16)),
               "l"(src + (size_t)r * sstride + c * 8) : "memory");
    }
}
// fp32 gmem [rows][64] -> fp16 hi -> 144B-row smem tile
__device__ __forceinline__ void cp_tile_h(char* dh, const float* src,
                                          size_t sstride, int rows, int t) {
    for (int i = t; i < rows * 8; i += 256) {
        int r = i >> 3, c = i & 7;
        const float* s = src + (size_t)r * sstride + c * 8;
        float4 v0 = *(const float4*)s;
        float4 v1 = *(const float4*)(s + 4);
        __align__(16) __half h[8];
        h[0] = __float2half_rn(v0.x); h[1] = __float2half_rn(v0.y);
        h[2] = __float2half_rn(v0.z); h[3] = __float2half_rn(v0.w);
        h[4] = __float2half_rn(v1.x); h[5] = __float2half_rn(v1.y);
        h[6] = __float2half_rn(v1.z); h[7] = __float2half_rn(v1.w);
        *(uint4*)(dh + r * 144 + c * 16) = *(uint4*)h;
    }
}

#define CP_COMMIT() asm volatile("cp.async.commit_group;" ::: "memory")
#define CP_WAIT0()  asm volatile("cp.async.wait_group 0;" ::: "memory")

#define TA32   (128 * 80)              // 10240
#define TB32   (64 * 80)               // 5120
#define TSZ128 (128 * 144)
#define TSZ64  (64 * 144)
#define STG_G  (3 * TA32)              // 30720 (k1/k5 stage)
#define STG_PV (2 * TA32 + TB32)       // 25600 (k4 stage)
#define STG_M1 (3 * TB32)              // 15360 (k2b stage)
#define SM_G   (2 * STG_G)             // 61440 (2-stage)
#define SM_PV  (2 * STG_PV)            // 51200
#define SM_M1  (2 * STG_M1)            // 30720
#define SM_K3  (TSZ64 + TSZ128)        // 27648

template<int STRIDE>
__device__ __forceinline__ uint32_t a_addr(uint32_t base, int wrow, int l) {
    return base + (uint32_t)(wrow + (l & 15)) * STRIDE + ((l >> 4) << 4);
}
template<int STRIDE>
__device__ __forceinline__ uint32_t b_addr(uint32_t base, int wrow, int l) {
    return base + (uint32_t)(wrow + (l & 7) + ((l >> 4) << 3)) * STRIDE + (((l >> 3) & 1) << 4);
}

// ---------------- prep kernels ---------------------------------------------
__global__ void __launch_bounds__(256) split_kernel(
    const float* __restrict__ in, __half* __restrict__ hi,
    __half* __restrict__ lo) {
    size_t i = ((size_t)blockIdx.x * 256 + threadIdx.x) * 4;
    float4 v = *(const float4*)(in + i);
    __align__(8) __half h[4], l[4];
    split2h(v.x, h[0], l[0]); split2h(v.y, h[1], l[1]);
    split2h(v.z, h[2], l[2]); split2h(v.w, h[3], l[3]);
    *(uint2*)(hi + i) = *(uint2*)h;
    *(uint2*)(lo + i) = *(uint2*)l;
}

__global__ void __launch_bounds__(256) transpose_h(
    const float* __restrict__ W, __half* __restrict__ th, int K, int N) {
    __shared__ float tile[32][33];
    int tx = threadIdx.x & 31, ty = threadIdx.x >> 5;
    int n0 = blockIdx.x * 32, k0 = blockIdx.y * 32;
    #pragma unroll
    for (int r = ty; r < 32; r += 8)
        tile[r][tx] = W[(size_t)(k0 + r) * N + n0 + tx];
    __syncthreads();
    #pragma unroll
    for (int r = ty; r < 32; r += 8)
        th[(size_t)(n0 + r) * K + k0 + tx] = __float2half_rn(tile[tx][r]);
}

// K^T (hi only) and V^T (split) from split qkv
__global__ void __launch_bounds__(256) kvt_kernel() {
    __shared__ __half th[32][33], tl[32][33];
    int tx = threadIdx.x & 31, ty = threadIdx.x >> 5;
    int bh = blockIdx.z, b = bh >> 4, h = bh & 15;
    int y0 = blockIdx.x * 32, d0 = blockIdx.y * 32;
    #pragma unroll
    for (int which = 0; which < 2; which++) {
        int off = 1024 + which * 1024;
        #pragma unroll
        for (int r = ty; r < 32; r += 8) {
            size_t s = (size_t)(b * SS + y0 + r) * L3E + off + h * 64 + d0 + tx;
            th[r][tx] = g_qh[s];
            if (which) tl[r][tx] = g_ql[s];
        }
        __syncthreads();
        #pragma unroll
        for (int r = ty; r < 32; r += 8) {
            size_t o = (size_t)(bh * 64 + d0 + r) * SS + y0 + tx;
            if (which) { g_vth[o] = th[tx][r]; g_vtl[o] = tl[tx][r]; }
            else       { g_kth[o] = th[tx][r]; }
        }
        __syncthreads();
    }
}

// ---------------- K1: qkv = x @ W_qkv + bias (2-stage, single-sync) ---------
__global__ void __launch_bounds__(256, 2) k1_gemm(const float* __restrict__ bias) {
    extern __shared__ char sm[];
    const int t = threadIdx.x, l = t & 31, wid = t >> 5;
    const int wm = (wid & 3) * 32, wn = (wid >> 2) * 64;
    const int n0 = blockIdx.x * 128, m0 = blockIdx.y * 128;
    uint32_t u = smem_u32(sm);
    uint32_t aAh = a_addr<80>(u, wm, l), aAl = a_addr<80>(u + TA32, wm, l);
    uint32_t aBh = b_addr<80>(u + 2 * TA32, wn, l);

    auto issue = [&](int kt) {
        uint32_t bo = u + (uint32_t)(kt & 1) * STG_G;
        int k0 = kt * 32;
        cp32(bo,            g_xh  + (size_t)m0 * 1024 + k0, 1024, 128, t);
        cp32(bo + TA32,     g_xl  + (size_t)m0 * 1024 + k0, 1024, 128, t);
        cp32(bo + 2 * TA32, g_wqh + (size_t)n0 * 1024 + k0, 1024, 128, t);
        CP_COMMIT();
    };

    float acc[2][8][4] = {};
    issue(0);
    for (int kt = 0; kt < 32; kt++) {
        CP_WAIT0();
        __syncthreads();
        if (kt + 1 < 32) issue(kt + 1);
        uint32_t bo = (uint32_t)(kt & 1) * STG_G;
        warp_kblk<4, 80, 2>(acc, aAh + bo, aAl + bo, aBh + bo);
    }
    // K-range columns (n in [1024,2048)) never consume their lo part: skip ql store.
    const bool kcols = (n0 >= 1024 && n0 < 2048);
    #pragma unroll
    for (int i = 0; i < 2; i++)
        #pragma unroll
        for (int jj = 0; jj < 8; jj++) {
            int m = m0 + wm + i * 16 + (l >> 2);
            int n = n0 + wn + jj * 8 + 2 * (l & 3);
            float b0 = __ldg(&bias[n]), b1 = __ldg(&bias[n + 1]);
            float v00 = acc[i][jj][0] + b0, v01 = acc[i][jj][1] + b1;
            float v10 = acc[i][jj][2] + b0, v11 = acc[i][jj][3] + b1;
            size_t o0 = (size_t)m * L3E + n, o1 = (size_t)(m + 8) * L3E + n;
            if (kcols) {
                __half2 h0, h1;
                h0.x = __float2half_rn(v00); h0.y = __float2half_rn(v01);
                h1.x = __float2half_rn(v10); h1.y = __float2half_rn(v11);
                *(__half2*)(g_qh + o0) = h0;
                *(__half2*)(g_qh + o1) = h1;
            } else {
                store_split2(g_qh, g_ql, o0, v00, v01);
                store_split2(g_qh, g_ql, o1, v10, v11);
            }
        }
}

// ---------------- K2b: M1^T = 0.125 * V^T K  (2-stage) -----------------------
__global__ void __launch_bounds__(256) k2b_ktv() {
    extern __shared__ char sm[];
    const int t = threadIdx.x, l = t & 31, wid = t >> 5;
    const int wm = (wid & 1) * 32, wn = (wid >> 1) * 16;
    const int bh = blockIdx.x;
    uint32_t u = smem_u32(sm);
    uint32_t aAh = a_addr<80>(u, wm, l), aAl = a_addr<80>(u + TB32, wm, l);
    uint32_t aBh = b_addr<80>(u + 2 * TB32, wn, l);

    const __half* Vh = g_vth + (size_t)bh * 64 * SS;
    const __half* Vl = g_vtl + (size_t)bh * 64 * SS;
    const __half* Kh = g_kth + (size_t)bh * 64 * SS;

    auto issue = [&](int kt) {
        uint32_t bo = u + (uint32_t)(kt & 1) * STG_M1;
        int k0 = kt * 32;
        cp32(bo,            Vh + k0, SS, 64, t);
        cp32(bo + TB32,     Vl + k0, SS, 64, t);
        cp32(bo + 2 * TB32, Kh + k0, SS, 64, t);
        CP_COMMIT();
    };

    float acc[2][2][4] = {};
    issue(0);
    for (int kt = 0; kt < 32; kt++) {
        CP_WAIT0();
        __syncthreads();
        if (kt + 1 < 32) issue(kt + 1);
        uint32_t bo = (uint32_t)(kt & 1) * STG_M1;
        warp_kblk<1, 80, 2>(acc, aAh + bo, aAl + bo, aBh + bo);
    }
    #pragma unroll
    for (int i = 0; i < 2; i++)
        #pragma unroll
        for (int jj = 0; jj < 2; jj++) {
            int m = wm + i * 16 + (l >> 2);
            int n = wn + jj * 8 + 2 * (l & 3);
            __half2 v0, v1;
            v0.x = __float2half_rn(0.125f * acc[i][jj][0]);
            v0.y = __float2half_rn(0.125f * acc[i][jj][1]);
            v1.x = __float2half_rn(0.125f * acc[i][jj][2]);
            v1.y = __float2half_rn(0.125f * acc[i][jj][3]);
            *(__half2*)(g_m1h + (size_t)bh * 4096 + (size_t)m * 64 + n)       = v0;
            *(__half2*)(g_m1h + (size_t)bh * 4096 + (size_t)(m + 8) * 64 + n) = v1;
        }
}

// ---------------- K3: P = scale * peq, plain fp16 ----------------------------
__global__ void __launch_bounds__(256) k3_peinit(const float* __restrict__ pe) {
    extern __shared__ char sm[];
    char *Ah = sm, *Bh = sm + TSZ64;
    const int t = threadIdx.x, l = t & 31, wid = t >> 5;
    const int wm = (wid & 1) * 32, wn = (wid >> 1) * 32;
    const int y0 = blockIdx.x * 128, x = blockIdx.y;
    uint32_t u = smem_u32(sm);
    uint32_t aA = a_addr<144>(u, wm, l);
    uint32_t aB = b_addr<144>(u + TSZ64, wn, l);

    for (int i = t; i < 64 * 8; i += 256) {
        int r = i >> 3, c = i & 7, b = r >> 4, h = r & 15;
        size_t s = (size_t)(b * SS + x) * L3E + h * 64 + c * 8;
        *(uint4*)(Ah + r * 144 + c * 16) = *(const uint4*)(g_qh + s);
    }
    cp_tile_h(Bh, pe + ((size_t)x * SS + y0) * 64, 64, 128, t);
    __syncthreads();

    float acc[2][4][4] = {};
    warp_kblk1<2, 144, 4>(acc, aA, aB);

    #pragma unroll
    for (int i = 0; i < 2; i++)
        #pragma unroll
        for (int jj = 0; jj < 4; jj++) {
            int bh = wm + i * 16 + (l >> 2);
            int y  = y0 + wn + jj * 8 + 2 * (l & 3);
            size_t a0 = ((size_t)bh * SS + x) * SS + y;
            size_t a1 = ((size_t)(bh + 8) * SS + x) * SS + y;
            __half2 v0, v1;
            v0.x = __float2half_rn(0.125f * acc[i][jj][0]);
            v0.y = __float2half_rn(0.125f * acc[i][jj][1]);
            v1.x = __float2half_rn(0.125f * acc[i][jj][2]);
            v1.y = __float2half_rn(0.125f * acc[i][jj][3]);
            *(__half2*)(g_P16 + a0) = v0;
            *(__half2*)(g_P16 + a1) = v1;
        }
}

// ---------------- K4: attn = P16 @ V + Q @ M1^T (2-stage) --------------------
__global__ void __launch_bounds__(256, 2) k4_pv() {
    extern __shared__ char sm[];
    const int t = threadIdx.x, l = t & 31, wid = t >> 5;
    const int wm = (wid & 3) * 32, wn = (wid >> 2) * 32;
    const int m0 = blockIdx.x * 128, bh = blockIdx.y, b = bh >> 4, h = bh & 15;
    uint32_t u = smem_u32(sm);
    uint32_t aA0 = a_addr<80>(u, wm, l), aA1 = a_addr<80>(u + TA32, wm, l);
    uint32_t aB0 = b_addr<80>(u + 2 * TA32, wn, l);

    const __half* Pp = g_P16 + ((size_t)bh * SS + m0) * SS;
    const __half* Vh = g_vth + (size_t)bh * 64 * SS;

    auto issue = [&](int kt) {
        uint32_t bo = u + (uint32_t)(kt & 1) * STG_PV;
        if (kt < 32) {
            int k0 = kt * 32;
            cp32(bo,            Pp + k0, SS, 128, t);
            cp32(bo + 2 * TA32, Vh + k0, SS, 64, t);
        } else {
            int c0 = (kt - 32) * 32;
            const __half* Qh = g_qh + (size_t)(b * SS + m0) * L3E + h * 64 + c0;
            const __half* Ql = g_ql + (size_t)(b * SS + m0) * L3E + h * 64 + c0;
            cp32(bo,            Qh, L3E, 128, t);
            cp32(bo + TA32,     Ql, L3E, 128, t);
            cp32(bo + 2 * TA32, g_m1h + (size_t)bh * 4096 + c0, 64, 64, t);
        }
        CP_COMMIT();
    };

    float acc[2][4][4] = {};
    issue(0);
    for (int kt = 0; kt < 34; kt++) {
        CP_WAIT0();
        __syncthreads();
        if (kt + 1 < 34) issue(kt + 1);
        uint32_t bo = (uint32_t)(kt & 1) * STG_PV;
        if (kt < 32) warp_kblk1<2, 80, 2>(acc, aA0 + bo, aB0 + bo);
        else         warp_kblk <2, 80, 2>(acc, aA0 + bo, aA1 + bo, aB0 + bo);
    }
    #pragma unroll
    for (int i = 0; i < 2; i++)
        #pragma unroll
        for (int jj = 0; jj < 4; jj++) {
            int m = m0 + wm + i * 16 + (l >> 2);
            int d = wn + jj * 8 + 2 * (l & 3);
            size_t o0 = (size_t)(b * SS + m) * EE + h * 64 + d;
            size_t o1 = (size_t)(b * SS + m + 8) * EE + h * 64 + d;
            store_split2(g_ah, g_al, o0, acc[i][jj][0], acc[i][jj][1]);
            store_split2(g_ah, g_al, o1, acc[i][jj][2], acc[i][jj][3]);
        }
}

// ---------------- K5: out = attn @ W_out + bias (2-stage) --------------------
__global__ void __launch_bounds__(256, 2) k5_gemm(const float* __restrict__ bias,
                                                  float* __restrict__ out) {
    extern __shared__ char sm[];
    const int t = threadIdx.x, l = t & 31, wid = t >> 5;
    const int wm = (wid & 3) * 32, wn = (wid >> 2) * 64;
    const int n0 = blockIdx.x * 128, m0 = blockIdx.y * 128;
    uint32_t u = smem_u32(sm);
    uint32_t aAh = a_addr<80>(u, wm, l), aAl = a_addr<80>(u + TA32, wm, l);
    uint32_t aBh = b_addr<80>(u + 2 * TA32, wn, l);

    auto issue = [&](int kt) {
        uint32_t bo = u + (uint32_t)(kt & 1) * STG_G;
        int k0 = kt * 32;
        cp32(bo,            g_ah  + (size_t)m0 * 1024 + k0, 1024, 128, t);
        cp32(bo + TA32,     g_al  + (size_t)m0 * 1024 + k0, 1024, 128, t);
        cp32(bo + 2 * TA32, g_woh + (size_t)n0 * 1024 + k0, 1024, 128, t);
        CP_COMMIT();
    };

    float acc[2][8][4] = {};
    issue(0);
    for (int kt = 0; kt < 32; kt++) {
        CP_WAIT0();
        __syncthreads();
        if (kt + 1 < 32) issue(kt + 1);
        uint32_t bo = (uint32_t)(kt & 1) * STG_G;
        warp_kblk<4, 80, 2>(acc, aAh + bo, aAl + bo, aBh + bo);
    }
    #pragma unroll
    for (int i = 0; i < 2; i++)
        #pragma unroll
        for (int jj = 0; jj < 8; jj++) {
            int m = m0 + wm + i * 16 + (l >> 2);
            int n = n0 + wn + jj * 8 + 2 * (l & 3);
            float b0 = __ldg(&bias[n]), b1 = __ldg(&bias[n + 1]);
            *(float2*)(out + (size_t)m * EE + n) =
                make_float2(acc[i][jj][0] + b0, acc[i][jj][1] + b1);
            *(float2*)(out + (size_t)(m + 8) * EE + n) =
                make_float2(acc[i][jj][2] + b0, acc[i][jj][3] + b1);
        }
}

// ---------------- launch -----------------------------------------------------
extern "C" void kernel_launch(void* const* d_in, const int* in_sizes, int n_in,
                              void* d_out, int out_size)
{
    const float* x     = (const float*)d_in[0];
    const float* W_qkv = (const float*)d_in[1];
    const float* b_qkv = (const float*)d_in[2];
    const float* pe    = (const float*)d_in[3];
    const float* W_out = (const float*)d_in[4];
    const float* b_out = (const float*)d_in[5];
    float* out = (float*)d_out;

    static cudaStream_t s1 = nullptr;
    static cudaEvent_t e0 = nullptr, e1 = nullptr, e2 = nullptr, e3 = nullptr;
    if (!s1) {
        cudaStreamCreateWithFlags(&s1, cudaStreamNonBlocking);
        cudaEventCreateWithFlags(&e0, cudaEventDisableTiming);
        cudaEventCreateWithFlags(&e1, cudaEventDisableTiming);
        cudaEventCreateWithFlags(&e2, cudaEventDisableTiming);
        cudaEventCreateWithFlags(&e3, cudaEventDisableTiming);

        cudaFuncSetAttribute(k1_gemm,   cudaFuncAttributeMaxDynamicSharedMemorySize, SM_G);
        cudaFuncSetAttribute(k2b_ktv,   cudaFuncAttributeMaxDynamicSharedMemorySize, SM_M1);
        cudaFuncSetAttribute(k3_peinit, cudaFuncAttributeMaxDynamicSharedMemorySize, SM_K3);
        cudaFuncSetAttribute(k4_pv,     cudaFuncAttributeMaxDynamicSharedMemorySize, SM_PV);
        cudaFuncSetAttribute(k5_gemm,   cudaFuncAttributeMaxDynamicSharedMemorySize, SM_G);
    }

    __half *xh, *xl, *wqh, *woh;
    cudaGetSymbolAddress((void**)&xh,  g_xh);  cudaGetSymbolAddress((void**)&xl,  g_xl);
    cudaGetSymbolAddress((void**)&wqh, g_wqh); cudaGetSymbolAddress((void**)&woh, g_woh);

    // fork: weight transposes on s1, x split on main
    cudaEventRecord(e0, 0);
    cudaStreamWaitEvent(s1, e0, 0);
    transpose_h<<<dim3(96, 32), 256, 0, s1>>>(W_qkv, wqh, 1024, 3072);
    transpose_h<<<dim3(32, 32), 256, 0, s1>>>(W_out, woh, 1024, 1024);
    cudaEventRecord(e1, s1);
    split_kernel<<<4194304 / 1024, 256>>>(x, xh, xl);
    cudaStreamWaitEvent(0, e1, 0);

    // k1 on main
    k1_gemm<<<dim3(24, 32), 256, SM_G>>>(b_qkv);

    // fork: kvt -> k2b on s1 (needs qkv); k3 on main (needs qh only)
    cudaEventRecord(e2, 0);
    cudaStreamWaitEvent(s1, e2, 0);
    kvt_kernel<<<dim3(32, 2, 64), 256, 0, s1>>>();
    k2b_ktv<<<64, 256, SM_M1, s1>>>();
    cudaEventRecord(e3, s1);
    k3_peinit<<<dim3(8, 1024), 256, SM_K3>>>(pe);
    cudaStreamWaitEvent(0, e3, 0);

    // join: k4, k5 on main
    k4_pv<<<dim3(8, 64), 256, SM_PV>>>();
    k5_gemm<<<dim3(8, 32), 256, SM_G>>>(b_out, out);
}

// round 17
// speedup vs baseline: 1.1742x; 1.1742x over previous
#include <cuda_runtime.h>
#include <cuda_fp16.h>
#include <cstdint>
#include <cstddef>

#define SS 1024
#define EE 1024
#define L3E 3072

// ---------------- scratch (device globals; no cudaMalloc allowed) ----------
__device__ __half g_xh[4194304];                    // x hi [tok][1024]
__device__ __half g_wqh[3145728];                   // W_qkv^T hi [n=3072][k=1024]
__device__ __half g_woh[1048576];                   // W_out^T hi [n=1024][k=1024]
__device__ __half g_qh[12582912], g_ql[12582912];   // qkv split [tok][3072]
__device__ __half g_kth[4194304];                   // K^T hi [bh][c=64][y=1024]
__device__ __half g_vth[4194304], g_vtl[4194304];   // V^T split [bh][d=64][y=1024]
__device__ __half g_m1h[262144];                    // M1^T=0.125*V^T K hi [bh][d][c]
__device__ __half g_P16[67108864];                  // P_pe fp16 [bh][x][y]
__device__ __half g_ah[4194304],  g_al[4194304];    // attn split [tok][1024]

// ---------------- helpers ---------------------------------------------------
__device__ __forceinline__ uint32_t smem_u32(const void* p) {
    uint32_t a;
    asm("{ .reg .u64 t; cvta.to.shared.u64 t, %1; cvt.u32.u64 %0, t; }" : "=r"(a) : "l"(p));
    return a;
}
__device__ __forceinline__ void split2h(float v, __half& h, __half& l) {
    h = __float2half_rn(v);
    l = __float2half_rn(v - __half2float(h));
}
__device__ __forceinline__ void store_split2(__half* Hp, __half* Lp,
                                             size_t off, float v0, float v1) {
    __half h0, l0, h1, l1;
    split2h(v0, h0, l0); split2h(v1, h1, l1);
    __half2 hh; hh.x = h0; hh.y = h1;
    __half2 ll; ll.x = l0; ll.y = l1;
    *(__half2*)(Hp + off) = hh;
    *(__half2*)(Lp + off) = ll;
}

__device__ __forceinline__ void ldsm4(uint32_t (&r)[4], uint32_t addr) {
    asm volatile("ldmatrix.sync.aligned.m8n8.x4.shared.b16 {%0,%1,%2,%3}, [%4];"
        : "=r"(r[0]), "=r"(r[1]), "=r"(r[2]), "=r"(r[3]) : "r"(addr));
}
__device__ __forceinline__ void mma16816(float (&d)[4], const uint32_t (&a)[4],
                                         uint32_t b0, uint32_t b1) {
    asm volatile(
        "mma.sync.aligned.m16n8k16.row.col.f32.f16.f16.f32 "
        "{%0,%1,%2,%3}, {%4,%5,%6,%7}, {%8,%9}, {%0,%1,%2,%3};"
        : "+f"(d[0]), "+f"(d[1]), "+f"(d[2]), "+f"(d[3])
        : "r"(a[0]), "r"(a[1]), "r"(a[2]), "r"(a[3]), "r"(b0), "r"(b1));
}

// warp-level K-block: A split (hi+lo) x B hi
template<int NJ, int STRIDE, int KS>
__device__ __forceinline__ void warp_kblk(float (&acc)[2][NJ * 2][4],
    uint32_t aAh, uint32_t aAl, uint32_t aBh)
{
    #pragma unroll
    for (int s = 0; s < KS; s++) {
        uint32_t ah[2][4], al[2][4];
        #pragma unroll
        for (int i = 0; i < 2; i++) {
            ldsm4(ah[i], aAh + i * 16 * STRIDE + s * 32);
            ldsm4(al[i], aAl + i * 16 * STRIDE + s * 32);
        }
        #pragma unroll
        for (int j = 0; j < NJ; j++) {
            uint32_t bh[4];
            ldsm4(bh, aBh + j * 16 * STRIDE + s * 32);
            #pragma unroll
            for (int i = 0; i < 2; i++) {
                mma16816(acc[i][2 * j],     ah[i], bh[0], bh[1]);
                mma16816(acc[i][2 * j + 1], ah[i], bh[2], bh[3]);
                mma16816(acc[i][2 * j],     al[i], bh[0], bh[1]);
                mma16816(acc[i][2 * j + 1], al[i], bh[2], bh[3]);
            }
        }
    }
}

// warp-level K-block, plain single fp16 A x B
template<int NJ, int STRIDE, int KS>
__device__ __forceinline__ void warp_kblk1(float (&acc)[2][NJ * 2][4],
    uint32_t aA, uint32_t aB)
{
    #pragma unroll
    for (int s = 0; s < KS; s++) {
        uint32_t a[2][4];
        #pragma unroll
        for (int i = 0; i < 2; i++)
            ldsm4(a[i], aA + i * 16 * STRIDE + s * 32);
        #pragma unroll
        for (int j = 0; j < NJ; j++) {
            uint32_t b[4];
            ldsm4(b, aB + j * 16 * STRIDE + s * 32);
            #pragma unroll
            for (int i = 0; i < 2; i++) {
                mma16816(acc[i][2 * j],     a[i], b[0], b[1]);
                mma16816(acc[i][2 * j + 1], a[i], b[2], b[3]);
            }
        }
    }
}

// async gmem [rows][32 fp16] -> smem rows of 80 bytes
__device__ __forceinline__ void cp32(uint32_t dst, const __half* src,
                                     size_t sstride, int rows, int t) {
    for (int i = t; i < rows * 4; i += 256) {
        int r = i >> 2, c = i & 3;
        asm volatile("cp.async.cg.shared.global [%0], [%1], 16;"
            :: "r"(dst + (uint32_t)(r * 80 + c * 16)),
               "l"(src + (size_t)r * sstride + c * 8) : "memory");
    }
}
// fp32 gmem [rows][64] -> fp16 hi -> 144B-row smem tile
__device__ __forceinline__ void cp_tile_h(char* dh, const float* src,
                                          size_t sstride, int rows, int t) {
    for (int i = t; i < rows * 8; i += 256) {
        int r = i >> 3, c = i & 7;
        const float* s = src + (size_t)r * sstride + c * 8;
        float4 v0 = *(const float4*)s;
        float4 v1 = *(const float4*)(s + 4);
        __align__(16) __half h[8];
        h[0] = __float2half_rn(v0.x); h[1] = __float2half_rn(v0.y);
        h[2] = __float2half_rn(v0.z); h[3] = __float2half_rn(v0.w);
        h[4] = __float2half_rn(v1.x); h[5] = __float2half_rn(v1.y);
        h[6] = __float2half_rn(v1.z); h[7] = __float2half_rn(v1.w);
        *(uint4*)(dh + r * 144 + c * 16) = *(uint4*)h;
    }
}

#define CP_COMMIT() asm volatile("cp.async.commit_group;" ::: "memory")
#define CP_WAIT0()  asm volatile("cp.async.wait_group 0;" ::: "memory")

#define TA32   (128 * 80)              // 10240
#define TB32   (64 * 80)               // 5120
#define TSZ128 (128 * 144)
#define TSZ64  (64 * 144)
#define STG_K1 (2 * TA32)              // 20480 (k1 stage: A-hi, B-hi)
#define STG_G  (3 * TA32)              // 30720 (k5 stage: Ah, Al, Bh)
#define STG_PV (2 * TA32 + TB32)       // 25600 (k4 stage)
#define STG_M1 (3 * TB32)              // 15360 (k2b stage)
#define SM_K1  (2 * STG_K1)            // 40960
#define SM_G   (2 * STG_G)             // 61440
#define SM_PV  (2 * STG_PV)            // 51200
#define SM_M1  (2 * STG_M1)            // 30720
#define SM_K3  (TSZ64 + TSZ128)        // 27648

template<int STRIDE>
__device__ __forceinline__ uint32_t a_addr(uint32_t base, int wrow, int l) {
    return base + (uint32_t)(wrow + (l & 15)) * STRIDE + ((l >> 4) << 4);
}
template<int STRIDE>
__device__ __forceinline__ uint32_t b_addr(uint32_t base, int wrow, int l) {
    return base + (uint32_t)(wrow + (l & 7) + ((l >> 4) << 3)) * STRIDE + (((l >> 3) & 1) << 4);
}

// ---------------- prep kernels ---------------------------------------------
// x: fp32 -> fp16 hi only
__global__ void __launch_bounds__(256) convert_x(
    const float* __restrict__ in, __half* __restrict__ hi) {
    size_t i = ((size_t)blockIdx.x * 256 + threadIdx.x) * 4;
    float4 v = *(const float4*)(in + i);
    __align__(8) __half h[4];
    h[0] = __float2half_rn(v.x); h[1] = __float2half_rn(v.y);
    h[2] = __float2half_rn(v.z); h[3] = __float2half_rn(v.w);
    *(uint2*)(hi + i) = *(uint2*)h;
}

__global__ void __launch_bounds__(256) transpose_h(
    const float* __restrict__ W, __half* __restrict__ th, int K, int N) {
    __shared__ float tile[32][33];
    int tx = threadIdx.x & 31, ty = threadIdx.x >> 5;
    int n0 = blockIdx.x * 32, k0 = blockIdx.y * 32;
    #pragma unroll
    for (int r = ty; r < 32; r += 8)
        tile[r][tx] = W[(size_t)(k0 + r) * N + n0 + tx];
    __syncthreads();
    #pragma unroll
    for (int r = ty; r < 32; r += 8)
        th[(size_t)(n0 + r) * K + k0 + tx] = __float2half_rn(tile[tx][r]);
}

// K^T (hi only) and V^T (split) from split qkv
__global__ void __launch_bounds__(256) kvt_kernel() {
    __shared__ __half th[32][33], tl[32][33];
    int tx = threadIdx.x & 31, ty = threadIdx.x >> 5;
    int bh = blockIdx.z, b = bh >> 4, h = bh & 15;
    int y0 = blockIdx.x * 32, d0 = blockIdx.y * 32;
    #pragma unroll
    for (int which = 0; which < 2; which++) {
        int off = 1024 + which * 1024;
        #pragma unroll
        for (int r = ty; r < 32; r += 8) {
            size_t s = (size_t)(b * SS + y0 + r) * L3E + off + h * 64 + d0 + tx;
            th[r][tx] = g_qh[s];
            if (which) tl[r][tx] = g_ql[s];
        }
        __syncthreads();
        #pragma unroll
        for (int r = ty; r < 32; r += 8) {
            size_t o = (size_t)(bh * 64 + d0 + r) * SS + y0 + tx;
            if (which) { g_vth[o] = th[tx][r]; g_vtl[o] = tl[tx][r]; }
            else       { g_kth[o] = th[tx][r]; }
        }
        __syncthreads();
    }
}

// ---------------- K1: qkv = x @ W_qkv + bias (plain fp16, 2-stage) ----------
__global__ void __launch_bounds__(256, 2) k1_gemm(const float* __restrict__ bias) {
    extern __shared__ char sm[];
    const int t = threadIdx.x, l = t & 31, wid = t >> 5;
    const int wm = (wid & 3) * 32, wn = (wid >> 2) * 64;
    const int n0 = blockIdx.x * 128, m0 = blockIdx.y * 128;
    uint32_t u = smem_u32(sm);
    uint32_t aA = a_addr<80>(u, wm, l);
    uint32_t aB = b_addr<80>(u + TA32, wn, l);

    auto issue = [&](int kt) {
        uint32_t bo = u + (uint32_t)(kt & 1) * STG_K1;
        int k0 = kt * 32;
        cp32(bo,        g_xh  + (size_t)m0 * 1024 + k0, 1024, 128, t);
        cp32(bo + TA32, g_wqh + (size_t)n0 * 1024 + k0, 1024, 128, t);
        CP_COMMIT();
    };

    float acc[2][8][4] = {};
    issue(0);
    for (int kt = 0; kt < 32; kt++) {
        CP_WAIT0();
        __syncthreads();
        if (kt + 1 < 32) issue(kt + 1);
        uint32_t bo = (uint32_t)(kt & 1) * STG_K1;
        warp_kblk1<4, 80, 2>(acc, aA + bo, aB + bo);
    }
    // K-range columns (n in [1024,2048)) never consume their lo part: skip ql store.
    const bool kcols = (n0 >= 1024 && n0 < 2048);
    #pragma unroll
    for (int i = 0; i < 2; i++)
        #pragma unroll
        for (int jj = 0; jj < 8; jj++) {
            int m = m0 + wm + i * 16 + (l >> 2);
            int n = n0 + wn + jj * 8 + 2 * (l & 3);
            float b0 = __ldg(&bias[n]), b1 = __ldg(&bias[n + 1]);
            float v00 = acc[i][jj][0] + b0, v01 = acc[i][jj][1] + b1;
            float v10 = acc[i][jj][2] + b0, v11 = acc[i][jj][3] + b1;
            size_t o0 = (size_t)m * L3E + n, o1 = (size_t)(m + 8) * L3E + n;
            if (kcols) {
                __half2 h0, h1;
                h0.x = __float2half_rn(v00); h0.y = __float2half_rn(v01);
                h1.x = __float2half_rn(v10); h1.y = __float2half_rn(v11);
                *(__half2*)(g_qh + o0) = h0;
                *(__half2*)(g_qh + o1) = h1;
            } else {
                store_split2(g_qh, g_ql, o0, v00, v01);
                store_split2(g_qh, g_ql, o1, v10, v11);
            }
        }
}

// ---------------- K2b: M1^T = 0.125 * V^T K  (2-stage) -----------------------
__global__ void __launch_bounds__(256) k2b_ktv() {
    extern __shared__ char sm[];
    const int t = threadIdx.x, l = t & 31, wid = t >> 5;
    const int wm = (wid & 1) * 32, wn = (wid >> 1) * 16;
    const int bh = blockIdx.x;
    uint32_t u = smem_u32(sm);
    uint32_t aAh = a_addr<80>(u, wm, l), aAl = a_addr<80>(u + TB32, wm, l);
    uint32_t aBh = b_addr<80>(u + 2 * TB32, wn, l);

    const __half* Vh = g_vth + (size_t)bh * 64 * SS;
    const __half* Vl = g_vtl + (size_t)bh * 64 * SS;
    const __half* Kh = g_kth + (size_t)bh * 64 * SS;

    auto issue = [&](int kt) {
        uint32_t bo = u + (uint32_t)(kt & 1) * STG_M1;
        int k0 = kt * 32;
        cp32(bo,            Vh + k0, SS, 64, t);
        cp32(bo + TB32,     Vl + k0, SS, 64, t);
        cp32(bo + 2 * TB32, Kh + k0, SS, 64, t);
        CP_COMMIT();
    };

    float acc[2][2][4] = {};
    issue(0);
    for (int kt = 0; kt < 32; kt++) {
        CP_WAIT0();
        __syncthreads();
        if (kt + 1 < 32) issue(kt + 1);
        uint32_t bo = (uint32_t)(kt & 1) * STG_M1;
        warp_kblk<1, 80, 2>(acc, aAh + bo, aAl + bo, aBh + bo);
    }
    #pragma unroll
    for (int i = 0; i < 2; i++)
        #pragma unroll
        for (int jj = 0; jj < 2; jj++) {
            int m = wm + i * 16 + (l >> 2);
            int n = wn + jj * 8 + 2 * (l & 3);
            __half2 v0, v1;
            v0.x = __float2half_rn(0.125f * acc[i][jj][0]);
            v0.y = __float2half_rn(0.125f * acc[i][jj][1]);
            v1.x = __float2half_rn(0.125f * acc[i][jj][2]);
            v1.y = __float2half_rn(0.125f * acc[i][jj][3]);
            *(__half2*)(g_m1h + (size_t)bh * 4096 + (size_t)m * 64 + n)       = v0;
            *(__half2*)(g_m1h + (size_t)bh * 4096 + (size_t)(m + 8) * 64 + n) = v1;
        }
}

// ---------------- K3: P = scale * peq, plain fp16 ----------------------------
__global__ void __launch_bounds__(256) k3_peinit(const float* __restrict__ pe) {
    extern __shared__ char sm[];
    char *Ah = sm, *Bh = sm + TSZ64;
    const int t = threadIdx.x, l = t & 31, wid = t >> 5;
    const int wm = (wid & 1) * 32, wn = (wid >> 1) * 32;
    const int y0 = blockIdx.x * 128, x = blockIdx.y;
    uint32_t u = smem_u32(sm);
    uint32_t aA = a_addr<144>(u, wm, l);
    uint32_t aB = b_addr<144>(u + TSZ64, wn, l);

    for (int i = t; i < 64 * 8; i += 256) {
        int r = i >> 3, c = i & 7, b = r >> 4, h = r & 15;
        size_t s = (size_t)(b * SS + x) * L3E + h * 64 + c * 8;
        *(uint4*)(Ah + r * 144 + c * 16) = *(const uint4*)(g_qh + s);
    }
    cp_tile_h(Bh, pe + ((size_t)x * SS + y0) * 64, 64, 128, t);
    __syncthreads();

    float acc[2][4][4] = {};
    warp_kblk1<2, 144, 4>(acc, aA, aB);

    #pragma unroll
    for (int i = 0; i < 2; i++)
        #pragma unroll
        for (int jj = 0; jj < 4; jj++) {
            int bh = wm + i * 16 + (l >> 2);
            int y  = y0 + wn + jj * 8 + 2 * (l & 3);
            size_t a0 = ((size_t)bh * SS + x) * SS + y;
            size_t a1 = ((size_t)(bh + 8) * SS + x) * SS + y;
            __half2 v0, v1;
            v0.x = __float2half_rn(0.125f * acc[i][jj][0]);
            v0.y = __float2half_rn(0.125f * acc[i][jj][1]);
            v1.x = __float2half_rn(0.125f * acc[i][jj][2]);
            v1.y = __float2half_rn(0.125f * acc[i][jj][3]);
            *(__half2*)(g_P16 + a0) = v0;
            *(__half2*)(g_P16 + a1) = v1;
        }
}

// ---------------- K4: attn = P16 @ V + Q @ M1^T (2-stage) --------------------
__global__ void __launch_bounds__(256, 2) k4_pv() {
    extern __shared__ char sm[];
    const int t = threadIdx.x, l = t & 31, wid = t >> 5;
    const int wm = (wid & 3) * 32, wn = (wid >> 2) * 32;
    const int m0 = blockIdx.x * 128, bh = blockIdx.y, b = bh >> 4, h = bh & 15;
    uint32_t u = smem_u32(sm);
    uint32_t aA0 = a_addr<80>(u, wm, l), aA1 = a_addr<80>(u + TA32, wm, l);
    uint32_t aB0 = b_addr<80>(u + 2 * TA32, wn, l);

    const __half* Pp = g_P16 + ((size_t)bh * SS + m0) * SS;
    const __half* Vh = g_vth + (size_t)bh * 64 * SS;

    auto issue = [&](int kt) {
        uint32_t bo = u + (uint32_t)(kt & 1) * STG_PV;
        if (kt < 32) {
            int k0 = kt * 32;
            cp32(bo,            Pp + k0, SS, 128, t);
            cp32(bo + 2 * TA32, Vh + k0, SS, 64, t);
        } else {
            int c0 = (kt - 32) * 32;
            const __half* Qh = g_qh + (size_t)(b * SS + m0) * L3E + h * 64 + c0;
            const __half* Ql = g_ql + (size_t)(b * SS + m0) * L3E + h * 64 + c0;
            cp32(bo,            Qh, L3E, 128, t);
            cp32(bo + TA32,     Ql, L3E, 128, t);
            cp32(bo + 2 * TA32, g_m1h + (size_t)bh * 4096 + c0, 64, 64, t);
        }
        CP_COMMIT();
    };

    float acc[2][4][4] = {};
    issue(0);
    for (int kt = 0; kt < 34; kt++) {
        CP_WAIT0();
        __syncthreads();
        if (kt + 1 < 34) issue(kt + 1);
        uint32_t bo = (uint32_t)(kt & 1) * STG_PV;
        if (kt < 32) warp_kblk1<2, 80, 2>(acc, aA0 + bo, aB0 + bo);
        else         warp_kblk <2, 80, 2>(acc, aA0 + bo, aA1 + bo, aB0 + bo);
    }
    #pragma unroll
    for (int i = 0; i < 2; i++)
        #pragma unroll
        for (int jj = 0; jj < 4; jj++) {
            int m = m0 + wm + i * 16 + (l >> 2);
            int d = wn + jj * 8 + 2 * (l & 3);
            size_t o0 = (size_t)(b * SS + m) * EE + h * 64 + d;
            size_t o1 = (size_t)(b * SS + m + 8) * EE + h * 64 + d;
            store_split2(g_ah, g_al, o0, acc[i][jj][0], acc[i][jj][1]);
            store_split2(g_ah, g_al, o1, acc[i][jj][2], acc[i][jj][3]);
        }
}

// ---------------- K5: out = attn @ W_out + bias (2-stage) --------------------
__global__ void __launch_bounds__(256, 2) k5_gemm(const float* __restrict__ bias,
                                                  float* __restrict__ out) {
    extern __shared__ char sm[];
    const int t = threadIdx.x, l = t & 31, wid = t >> 5;
    const int wm = (wid & 3) * 32, wn = (wid >> 2) * 64;
    const int n0 = blockIdx.x * 128, m0 = blockIdx.y * 128;
    uint32_t u = smem_u32(sm);
    uint32_t aAh = a_addr<80>(u, wm, l), aAl = a_addr<80>(u + TA32, wm, l);
    uint32_t aBh = b_addr<80>(u + 2 * TA32, wn, l);

    auto issue = [&](int kt) {
        uint32_t bo = u + (uint32_t)(kt & 1) * STG_G;
        int k0 = kt * 32;
        cp32(bo,            g_ah  + (size_t)m0 * 1024 + k0, 1024, 128, t);
        cp32(bo + TA32,     g_al  + (size_t)m0 * 1024 + k0, 1024, 128, t);
        cp32(bo + 2 * TA32, g_woh + (size_t)n0 * 1024 + k0, 1024, 128, t);
        CP_COMMIT();
    };

    float acc[2][8][4] = {};
    issue(0);
    for (int kt = 0; kt < 32; kt++) {
        CP_WAIT0();
        __syncthreads();
        if (kt + 1 < 32) issue(kt + 1);
        uint32_t bo = (uint32_t)(kt & 1) * STG_G;
        warp_kblk<4, 80, 2>(acc, aAh + bo, aAl + bo, aBh + bo);
    }
    #pragma unroll
    for (int i = 0; i < 2; i++)
        #pragma unroll
        for (int jj = 0; jj < 8; jj++) {
            int m = m0 + wm + i * 16 + (l >> 2);
            int n = n0 + wn + jj * 8 + 2 * (l & 3);
            float b0 = __ldg(&bias[n]), b1 = __ldg(&bias[n + 1]);
            *(float2*)(out + (size_t)m * EE + n) =
                make_float2(acc[i][jj][0] + b0, acc[i][jj][1] + b1);
            *(float2*)(out + (size_t)(m + 8) * EE + n) =
                make_float2(acc[i][jj][2] + b0, acc[i][jj][3] + b1);
        }
}

// ---------------- launch -----------------------------------------------------
extern "C" void kernel_launch(void* const* d_in, const int* in_sizes, int n_in,
                              void* d_out, int out_size)
{
    const float* x     = (const float*)d_in[0];
    const float* W_qkv = (const float*)d_in[1];
    const float* b_qkv = (const float*)d_in[2];
    const float* pe    = (const float*)d_in[3];
    const float* W_out = (const float*)d_in[4];
    const float* b_out = (const float*)d_in[5];
    float* out = (float*)d_out;

    static cudaStream_t s1 = nullptr;
    static cudaEvent_t e0 = nullptr, e1 = nullptr, e2 = nullptr, e3 = nullptr;
    if (!s1) {
        cudaStreamCreateWithFlags(&s1, cudaStreamNonBlocking);
        cudaEventCreateWithFlags(&e0, cudaEventDisableTiming);
        cudaEventCreateWithFlags(&e1, cudaEventDisableTiming);
        cudaEventCreateWithFlags(&e2, cudaEventDisableTiming);
        cudaEventCreateWithFlags(&e3, cudaEventDisableTiming);

        cudaFuncSetAttribute(k1_gemm,   cudaFuncAttributeMaxDynamicSharedMemorySize, SM_K1);
        cudaFuncSetAttribute(k2b_ktv,   cudaFuncAttributeMaxDynamicSharedMemorySize, SM_M1);
        cudaFuncSetAttribute(k3_peinit, cudaFuncAttributeMaxDynamicSharedMemorySize, SM_K3);
        cudaFuncSetAttribute(k4_pv,     cudaFuncAttributeMaxDynamicSharedMemorySize, SM_PV);
        cudaFuncSetAttribute(k5_gemm,   cudaFuncAttributeMaxDynamicSharedMemorySize, SM_G);
    }

    __half *xh, *wqh, *woh;
    cudaGetSymbolAddress((void**)&xh,  g_xh);
    cudaGetSymbolAddress((void**)&wqh, g_wqh);
    cudaGetSymbolAddress((void**)&woh, g_woh);

    // fork: weight transposes on s1, x convert on main
    cudaEventRecord(e0, 0);
    cudaStreamWaitEvent(s1, e0, 0);
    transpose_h<<<dim3(96, 32), 256, 0, s1>>>(W_qkv, wqh, 1024, 3072);
    transpose_h<<<dim3(32, 32), 256, 0, s1>>>(W_out, woh, 1024, 1024);
    cudaEventRecord(e1, s1);
    convert_x<<<4194304 / 1024, 256>>>(x, xh);
    cudaStreamWaitEvent(0, e1, 0);

    // k1 on main
    k1_gemm<<<dim3(24, 32), 256, SM_K1>>>(b_qkv);

    // fork: kvt -> k2b on s1 (needs qkv); k3 on main (needs qh only)
    cudaEventRecord(e2, 0);
    cudaStreamWaitEvent(s1, e2, 0);
    kvt_kernel<<<dim3(32, 2, 64), 256, 0, s1>>>();
    k2b_ktv<<<64, 256, SM_M1, s1>>>();
    cudaEventRecord(e3, s1);
    k3_peinit<<<dim3(8, 1024), 256, SM_K3>>>(pe);
    cudaStreamWaitEvent(0, e3, 0);

    // join: k4, k5 on main
    k4_pv<<<dim3(8, 64), 256, SM_PV>>>();
    k5_gemm<<<dim3(8, 32), 256, SM_G>>>(b_out, out);
}